// round 2
// baseline (speedup 1.0000x reference)
#include <cuda_runtime.h>

#define NN 50000
#define EE 800000
#define HH 64
#define BB 50
#define LL 7
#define NSCAN_BLK 49   // ceil(50000/1024)

// ---------------- scratch (device globals; no allocations) ----------------
__device__ float g_h0[NN * 32];
__device__ float g_hA[NN * 64];
__device__ float g_hB[NN * 64];
__device__ int   g_rowptr[NN + 1];
__device__ int   g_cursor[NN];
__device__ int   g_rank[EE];
__device__ int   g_csr[EE];
__device__ int   g_bsum[64];
__device__ float g_pool[BB * HH];
__device__ int   g_cnt[BB];

// ---------------- f32x2 helpers ----------------
typedef unsigned long long u64;
__device__ __forceinline__ u64 splat2(float x) {
    u64 r; asm("mov.b64 %0,{%1,%1};" : "=l"(r) : "f"(x)); return r;
}
__device__ __forceinline__ u64 fma2(u64 a, u64 b, u64 c) {
    u64 d; asm("fma.rn.f32x2 %0,%1,%2,%3;" : "=l"(d) : "l"(a), "l"(b), "l"(c)); return d;
}
__device__ __forceinline__ u64 add2(u64 a, u64 b) {
    u64 d; asm("add.rn.f32x2 %0,%1,%2;" : "=l"(d) : "l"(a), "l"(b)); return d;
}
__device__ __forceinline__ float2 unpk(u64 v) {
    float2 f; asm("mov.b64 {%0,%1},%2;" : "=f"(f.x), "=f"(f.y) : "l"(v)); return f;
}

// ---------------- init / input prep ----------------
__global__ void init_kernel() {
    int i = blockIdx.x * blockDim.x + threadIdx.x;
    if (i < NN) g_cursor[i] = 0;
    if (i < BB * HH) g_pool[i] = 0.f;
    if (i < BB) g_cnt[i] = 0;
}

__global__ void build_h0(const float* __restrict__ x, const float* __restrict__ pos) {
    int i = blockIdx.x * blockDim.x + threadIdx.x;
    if (i >= NN * 32) return;
    int v = i >> 5, c = i & 31;
    g_h0[i] = (c < 29) ? x[v * 29 + c] : pos[v * 3 + (c - 29)];
}

// ---------------- CSR build ----------------
__global__ void hist_kernel(const int* __restrict__ dst) {
    int e = blockIdx.x * blockDim.x + threadIdx.x;
    if (e < EE) g_rank[e] = atomicAdd(&g_cursor[dst[e]], 1);
}

__global__ void scanA_kernel() {
    __shared__ int wsum[32];
    int i = blockIdx.x * 1024 + threadIdx.x;
    int lane = threadIdx.x & 31, wid = threadIdx.x >> 5;
    int xx = (i < NN) ? g_cursor[i] : 0;
    #pragma unroll
    for (int o = 1; o < 32; o <<= 1) {
        int y = __shfl_up_sync(0xffffffffu, xx, o);
        if (lane >= o) xx += y;
    }
    if (lane == 31) wsum[wid] = xx;
    __syncthreads();
    if (wid == 0) {
        int s = wsum[lane];
        #pragma unroll
        for (int o = 1; o < 32; o <<= 1) {
            int y = __shfl_up_sync(0xffffffffu, s, o);
            if (lane >= o) s += y;
        }
        wsum[lane] = s;
    }
    __syncthreads();
    int incl = xx + (wid ? wsum[wid - 1] : 0);
    if (i < NN) g_rowptr[i + 1] = incl;
    if (threadIdx.x == 1023) g_bsum[blockIdx.x] = incl;
}

__global__ void scanB_kernel() {
    int s = 0;
    for (int b = 0; b < NSCAN_BLK; b++) { int t = g_bsum[b]; g_bsum[b] = s; s += t; }
}

__global__ void scanC_kernel() {
    int i = blockIdx.x * 1024 + threadIdx.x;
    if (i < NN) g_rowptr[i + 1] += g_bsum[blockIdx.x];
    if (i == 0) g_rowptr[0] = 0;
}

__global__ void scatter_kernel(const int* __restrict__ src, const int* __restrict__ dst) {
    int e = blockIdx.x * blockDim.x + threadIdx.x;
    if (e >= EE) return;
    int d = dst[e];
    g_csr[g_rowptr[d] + g_rank[e]] = src[e];
}

// ---------------- fused GIN layer: node-per-lane GEMV with f32x2 ----------------
// 128 threads = 4 warps; warp handles 32 nodes (one per lane in the GEMV phase).
// z-tile in SMEM per warp: [64 features][33] (padded) -> conflict-free column reads.
// Weights broadcast via LDS.64, accumulators packed f32x2 (32 regs = 64 outputs).
template <int C, bool RELU_OUT>
__global__ void __launch_bounds__(128) gin_layer(
    const float* __restrict__ h_in, float* __restrict__ h_out,
    const float* __restrict__ W1, const float* __restrict__ b1,
    const float* __restrict__ W2, const float* __restrict__ b2)
{
    extern __shared__ float smem[];
    float* sW1 = smem;                 // C*64
    float* sW2 = sW1 + C * 64;         // 64*64
    float* sb1 = sW2 + 4096;           // 64
    float* sb2 = sb1 + 64;             // 64
    float* zt  = sb2 + 64 + (threadIdx.x >> 5) * (64 * 33);

    for (int i = threadIdx.x; i < C * 64; i += 128) sW1[i] = W1[i];
    for (int i = threadIdx.x; i < 64 * 64; i += 128) sW2[i] = W2[i];
    if (threadIdx.x < 64) { sb1[threadIdx.x] = b1[threadIdx.x]; sb2[threadIdx.x] = b2[threadIdx.x]; }
    __syncthreads();

    const int lane  = threadIdx.x & 31;
    const int vbase = (blockIdx.x * 4 + (threadIdx.x >> 5)) * 32;

    // --- gather: z[v] = h[v] + sum_{e:dst==v} h[src_e]; write into z-tile ---
    if (C == 64) {
        const u64* hp = (const u64*)h_in;  // float2 per lane: features (2l, 2l+1)
        for (int n = 0; n < 32; n++) {
            int v = vbase + n;
            if (v >= NN) break;
            u64 z = __ldg(hp + (size_t)v * 32 + lane);
            int e0 = __ldg(&g_rowptr[v]), e1 = __ldg(&g_rowptr[v + 1]);
            for (int e = e0; e < e1; e++) {
                int s = __ldg(&g_csr[e]);
                z = add2(z, __ldg(hp + (size_t)s * 32 + lane));
            }
            float2 f = unpk(z);
            zt[(2 * lane) * 33 + n]     = f.x;
            zt[(2 * lane + 1) * 33 + n] = f.y;
        }
    } else {
        for (int n = 0; n < 32; n++) {
            int v = vbase + n;
            if (v >= NN) break;
            float z = __ldg(&h_in[(size_t)v * 32 + lane]);
            int e0 = __ldg(&g_rowptr[v]), e1 = __ldg(&g_rowptr[v + 1]);
            for (int e = e0; e < e1; e++) {
                int s = __ldg(&g_csr[e]);
                z += __ldg(&h_in[(size_t)s * 32 + lane]);
            }
            zt[lane * 33 + n] = z;
        }
    }
    __syncwarp();

    // --- GEMV1: t = relu(z @ W1 + b1), node = lane ---
    u64 acc[32];
    {
        const u64* bp = (const u64*)sb1;
        #pragma unroll
        for (int jj = 0; jj < 32; jj++) acc[jj] = bp[jj];
    }
    for (int c = 0; c < C; c++) {
        u64 zz = splat2(zt[c * 33 + lane]);
        const u64* w = (const u64*)sW1 + c * 32;
        #pragma unroll
        for (int jj = 0; jj < 32; jj++) acc[jj] = fma2(zz, w[jj], acc[jj]);
    }
    __syncwarp();
    #pragma unroll
    for (int jj = 0; jj < 32; jj++) {
        float2 f = unpk(acc[jj]);
        zt[(2 * jj) * 33 + lane]     = fmaxf(f.x, 0.f);
        zt[(2 * jj + 1) * 33 + lane] = fmaxf(f.y, 0.f);
    }
    __syncwarp();

    // --- GEMV2: o = t @ W2 + b2 ---
    {
        const u64* bp = (const u64*)sb2;
        #pragma unroll
        for (int jj = 0; jj < 32; jj++) acc[jj] = bp[jj];
    }
    for (int c = 0; c < 64; c++) {
        u64 zz = splat2(zt[c * 33 + lane]);
        const u64* w = (const u64*)sW2 + c * 32;
        #pragma unroll
        for (int jj = 0; jj < 32; jj++) acc[jj] = fma2(zz, w[jj], acc[jj]);
    }

    int v = vbase + lane;
    if (v < NN) {
        float2* out2 = (float2*)h_out + (size_t)v * 32;
        #pragma unroll
        for (int jj = 0; jj < 32; jj++) {
            float2 f = unpk(acc[jj]);
            if (RELU_OUT) { f.x = fmaxf(f.x, 0.f); f.y = fmaxf(f.y, 0.f); }
            out2[jj] = f;
        }
    }
}

// ---------------- pooling + final linear ----------------
__global__ void pool_kernel(const float* __restrict__ h, const int* __restrict__ batch) {
    int gtid = blockIdx.x * blockDim.x + threadIdx.x;
    int v = gtid >> 5, lane = threadIdx.x & 31;
    if (v >= NN) return;
    int g = __ldg(&batch[v]);
    float2 val = *(const float2*)&h[(size_t)v * HH + 2 * lane];
    atomicAdd((float2*)&g_pool[g * HH + 2 * lane], val);
    if (lane == 0) atomicAdd(&g_cnt[g], 1);
}

__global__ void final_kernel(const float* __restrict__ lin_w,
                             const float* __restrict__ lin_b,
                             float* __restrict__ out) {
    int gtid = blockIdx.x * blockDim.x + threadIdx.x;
    int g = gtid >> 5, lane = threadIdx.x & 31;
    if (g >= BB) return;
    float s = g_pool[g * HH + lane] * __ldg(&lin_w[lane]) +
              g_pool[g * HH + 32 + lane] * __ldg(&lin_w[32 + lane]);
    #pragma unroll
    for (int o = 16; o; o >>= 1) s += __shfl_xor_sync(0xffffffffu, s, o);
    if (lane == 0) out[g] = s / fmaxf((float)g_cnt[g], 1.f) + lin_b[0];
}

// ---------------- launch ----------------
extern "C" void kernel_launch(void* const* d_in, const int* in_sizes, int n_in,
                              void* d_out, int out_size) {
    const float* x     = (const float*)d_in[0];
    const float* pos   = (const float*)d_in[1];
    const int*   ei    = (const int*)d_in[2];
    const int*   batch = (const int*)d_in[3];
    const float* W1f   = (const float*)d_in[4];
    const float* W1r   = (const float*)d_in[5];
    const float* b1    = (const float*)d_in[6];
    const float* W2    = (const float*)d_in[7];
    const float* b2    = (const float*)d_in[8];
    const float* lin_w = (const float*)d_in[9];
    const float* lin_b = (const float*)d_in[10];
    float* out = (float*)d_out;

    const int* src = ei;
    const int* dst = ei + EE;

    float *h0, *hA, *hB;
    cudaGetSymbolAddress((void**)&h0, g_h0);
    cudaGetSymbolAddress((void**)&hA, g_hA);
    cudaGetSymbolAddress((void**)&hB, g_hB);

    // dynamic smem sizes (floats): W1 + W2 + 128 bias + 4 warp tiles of 64*33
    const int smem32 = (32 * 64 + 4096 + 128 + 4 * 64 * 33) * 4;
    const int smem64 = (64 * 64 + 4096 + 128 + 4 * 64 * 33) * 4;
    cudaFuncSetAttribute(gin_layer<32, true>,  cudaFuncAttributeMaxDynamicSharedMemorySize, smem32);
    cudaFuncSetAttribute(gin_layer<64, true>,  cudaFuncAttributeMaxDynamicSharedMemorySize, smem64);
    cudaFuncSetAttribute(gin_layer<64, false>, cudaFuncAttributeMaxDynamicSharedMemorySize, smem64);

    init_kernel<<<(NN + 255) / 256, 256>>>();
    build_h0<<<(NN * 32 + 255) / 256, 256>>>(x, pos);
    hist_kernel<<<(EE + 255) / 256, 256>>>(dst);
    scanA_kernel<<<NSCAN_BLK, 1024>>>();
    scanB_kernel<<<1, 1>>>();
    scanC_kernel<<<NSCAN_BLK, 1024>>>();
    scatter_kernel<<<(EE + 255) / 256, 256>>>(src, dst);

    const int NB = (NN + 127) / 128;  // 4 warps x 32 nodes per block

    gin_layer<32, true><<<NB, 128, smem32>>>(h0, hA, W1f, b1, W2, b2);

    float* cur = hA;
    float* nxt = hB;
    for (int l = 1; l < LL; l++) {
        const float* w1 = W1r + (size_t)(l - 1) * HH * HH;
        if (l < LL - 1)
            gin_layer<64, true><<<NB, 128, smem64>>>(cur, nxt, w1, b1 + l * HH,
                                                     W2 + (size_t)l * HH * HH, b2 + l * HH);
        else
            gin_layer<64, false><<<NB, 128, smem64>>>(cur, nxt, w1, b1 + l * HH,
                                                      W2 + (size_t)l * HH * HH, b2 + l * HH);
        float* t = cur; cur = nxt; nxt = t;
    }

    pool_kernel<<<(NN * 32 + 255) / 256, 256>>>(cur, batch);
    final_kernel<<<(BB * 32 + 255) / 256, 256>>>(lin_w, lin_b, out);
}

// round 3
// speedup vs baseline: 1.1502x; 1.1502x over previous
#include <cuda_runtime.h>

#define NN 50000
#define EE 800000
#define HH 64
#define BB 50
#define LL 7
#define NSCAN_BLK 49   // ceil(50000/1024)

// ---------------- scratch (device globals; no allocations) ----------------
__device__ float g_h0[NN * 32];
__device__ float g_hA[NN * 64];
__device__ float g_hB[NN * 64];
__device__ int   g_rowptr[NN + 1];
__device__ int   g_cursor[NN];
__device__ int   g_rank[EE];
__device__ int   g_csr[EE];
__device__ int   g_bsum[64];
__device__ float g_pool[BB * HH];
__device__ int   g_cnt[BB];

// ---------------- f32x2 helpers ----------------
typedef unsigned long long u64;
__device__ __forceinline__ u64 splat2(float x) {
    u64 r; asm("mov.b64 %0,{%1,%1};" : "=l"(r) : "f"(x)); return r;
}
__device__ __forceinline__ u64 fma2(u64 a, u64 b, u64 c) {
    u64 d; asm("fma.rn.f32x2 %0,%1,%2,%3;" : "=l"(d) : "l"(a), "l"(b), "l"(c)); return d;
}
__device__ __forceinline__ u64 add2(u64 a, u64 b) {
    u64 d; asm("add.rn.f32x2 %0,%1,%2;" : "=l"(d) : "l"(a), "l"(b)); return d;
}
__device__ __forceinline__ float2 unpk(u64 v) {
    float2 f; asm("mov.b64 {%0,%1},%2;" : "=f"(f.x), "=f"(f.y) : "l"(v)); return f;
}
__device__ __forceinline__ u64 pk2(float x, float y) {
    u64 r; asm("mov.b64 %0,{%1,%2};" : "=l"(r) : "f"(x), "f"(y)); return r;
}

// ---------------- init / input prep ----------------
__global__ void init_kernel() {
    int i = blockIdx.x * blockDim.x + threadIdx.x;
    if (i < NN) g_cursor[i] = 0;
    if (i < BB * HH) g_pool[i] = 0.f;
    if (i < BB) g_cnt[i] = 0;
}

__global__ void build_h0(const float* __restrict__ x, const float* __restrict__ pos) {
    int i = blockIdx.x * blockDim.x + threadIdx.x;
    if (i >= NN * 32) return;
    int v = i >> 5, c = i & 31;
    g_h0[i] = (c < 29) ? x[v * 29 + c] : pos[v * 3 + (c - 29)];
}

// ---------------- CSR build ----------------
__global__ void hist_kernel(const int* __restrict__ dst) {
    int e = blockIdx.x * blockDim.x + threadIdx.x;
    if (e < EE) g_rank[e] = atomicAdd(&g_cursor[dst[e]], 1);
}

__global__ void scanA_kernel() {
    __shared__ int wsum[32];
    int i = blockIdx.x * 1024 + threadIdx.x;
    int lane = threadIdx.x & 31, wid = threadIdx.x >> 5;
    int xx = (i < NN) ? g_cursor[i] : 0;
    #pragma unroll
    for (int o = 1; o < 32; o <<= 1) {
        int y = __shfl_up_sync(0xffffffffu, xx, o);
        if (lane >= o) xx += y;
    }
    if (lane == 31) wsum[wid] = xx;
    __syncthreads();
    if (wid == 0) {
        int s = wsum[lane];
        #pragma unroll
        for (int o = 1; o < 32; o <<= 1) {
            int y = __shfl_up_sync(0xffffffffu, s, o);
            if (lane >= o) s += y;
        }
        wsum[lane] = s;
    }
    __syncthreads();
    int incl = xx + (wid ? wsum[wid - 1] : 0);
    if (i < NN) g_rowptr[i + 1] = incl;
    if (threadIdx.x == 1023) g_bsum[blockIdx.x] = incl;
}

__global__ void scanB_kernel() {
    int s = 0;
    for (int b = 0; b < NSCAN_BLK; b++) { int t = g_bsum[b]; g_bsum[b] = s; s += t; }
}

__global__ void scanC_kernel() {
    int i = blockIdx.x * 1024 + threadIdx.x;
    if (i < NN) g_rowptr[i + 1] += g_bsum[blockIdx.x];
    if (i == 0) g_rowptr[0] = 0;
}

__global__ void scatter_kernel(const int* __restrict__ src, const int* __restrict__ dst) {
    int e = blockIdx.x * blockDim.x + threadIdx.x;
    if (e >= EE) return;
    int d = dst[e];
    g_csr[g_rowptr[d] + g_rank[e]] = src[e];
}

// ---------------- fused GIN layer ----------------
// 256 threads = 8 warps; each warp owns 4 nodes (12500 warps chip-wide for
// gather latency hiding). z/t tiles are per-warp SMEM regions (syncwarp only).
// GEMV: lane owns output-feature pair (2l,2l+1); z broadcast via uniform LDS,
// weights via lane-striped LDS.64, accumulation in packed f32x2.
template <int C, bool RELU_OUT>
__global__ void __launch_bounds__(256) gin_layer(
    const float* __restrict__ h_in, float* __restrict__ h_out,
    const float* __restrict__ W1, const float* __restrict__ b1,
    const float* __restrict__ W2, const float* __restrict__ b2)
{
    extern __shared__ float smem[];
    float* sW1 = smem;                    // C*64
    float* sW2 = sW1 + C * 64;            // 64*64
    float* sb1 = sW2 + 4096;              // 64
    float* sb2 = sb1 + 64;                // 64
    float* warpbase = sb2 + 64 + (threadIdx.x >> 5) * (8 * 64);
    float* zt = warpbase;                 // 4 nodes x 64 (layer0: x 32)
    float* tt = warpbase + 4 * 64;        // 4 nodes x 64

    for (int i = threadIdx.x; i < C * 64; i += 256) sW1[i] = W1[i];
    for (int i = threadIdx.x; i < 64 * 64; i += 256) sW2[i] = W2[i];
    if (threadIdx.x < 64) { sb1[threadIdx.x] = b1[threadIdx.x]; sb2[threadIdx.x] = b2[threadIdx.x]; }
    __syncthreads();

    const int lane  = threadIdx.x & 31;
    const int vbase = (blockIdx.x * 8 + (threadIdx.x >> 5)) * 4;

    // --- gather: z[v] = h[v] + sum_{e:dst==v} h[src_e] -> z tile ---
    if (C == 64) {
        const u64* hp = (const u64*)h_in;  // lane holds feature pair (2l,2l+1)
        #pragma unroll
        for (int n = 0; n < 4; n++) {
            int v = vbase + n;
            if (v >= NN) break;
            u64 z = __ldg(hp + (size_t)v * 32 + lane);
            int e0 = __ldg(&g_rowptr[v]), e1 = __ldg(&g_rowptr[v + 1]);
            int e = e0;
            for (; e + 1 < e1; e += 2) {
                int s0 = __ldg(&g_csr[e]);
                int s1 = __ldg(&g_csr[e + 1]);
                u64 a = __ldg(hp + (size_t)s0 * 32 + lane);
                u64 b = __ldg(hp + (size_t)s1 * 32 + lane);
                z = add2(z, add2(a, b));
            }
            if (e < e1) {
                int s = __ldg(&g_csr[e]);
                z = add2(z, __ldg(hp + (size_t)s * 32 + lane));
            }
            ((u64*)(zt + n * 64))[lane] = z;   // STS.64, contiguous
        }
    } else {
        #pragma unroll
        for (int n = 0; n < 4; n++) {
            int v = vbase + n;
            if (v >= NN) break;
            float z = __ldg(&h_in[(size_t)v * 32 + lane]);
            int e0 = __ldg(&g_rowptr[v]), e1 = __ldg(&g_rowptr[v + 1]);
            int e = e0;
            for (; e + 1 < e1; e += 2) {
                int s0 = __ldg(&g_csr[e]);
                int s1 = __ldg(&g_csr[e + 1]);
                z += __ldg(&h_in[(size_t)s0 * 32 + lane]) +
                     __ldg(&h_in[(size_t)s1 * 32 + lane]);
            }
            if (e < e1) {
                int s = __ldg(&g_csr[e]);
                z += __ldg(&h_in[(size_t)s * 32 + lane]);
            }
            zt[n * (C == 32 ? 32 : 64) + lane] = z;
        }
    }
    __syncwarp();

    const int ZS = (C == 32) ? 32 : 64;   // z-tile row stride for GEMV1

    // --- GEMV1: t = relu(z @ W1 + b1) ---
    u64 acc[4];
    {
        u64 bias = ((const u64*)sb1)[lane];
        #pragma unroll
        for (int n = 0; n < 4; n++) acc[n] = bias;
    }
    for (int c4 = 0; c4 < C; c4 += 4) {
        float4 zq[4];
        #pragma unroll
        for (int n = 0; n < 4; n++)
            zq[n] = *(const float4*)&zt[n * ZS + c4];   // uniform-address broadcast
        #pragma unroll
        for (int k = 0; k < 4; k++) {
            u64 w = ((const u64*)(sW1 + (c4 + k) * 64))[lane];
            #pragma unroll
            for (int n = 0; n < 4; n++) {
                float zc = ((const float*)&zq[n])[k];
                acc[n] = fma2(splat2(zc), w, acc[n]);
            }
        }
    }
    #pragma unroll
    for (int n = 0; n < 4; n++) {
        float2 f = unpk(acc[n]);
        ((u64*)(tt + n * 64))[lane] = pk2(fmaxf(f.x, 0.f), fmaxf(f.y, 0.f));
    }
    __syncwarp();

    // --- GEMV2: o = t @ W2 + b2 ---
    {
        u64 bias = ((const u64*)sb2)[lane];
        #pragma unroll
        for (int n = 0; n < 4; n++) acc[n] = bias;
    }
    for (int c4 = 0; c4 < 64; c4 += 4) {
        float4 zq[4];
        #pragma unroll
        for (int n = 0; n < 4; n++)
            zq[n] = *(const float4*)&tt[n * 64 + c4];
        #pragma unroll
        for (int k = 0; k < 4; k++) {
            u64 w = ((const u64*)(sW2 + (c4 + k) * 64))[lane];
            #pragma unroll
            for (int n = 0; n < 4; n++) {
                float zc = ((const float*)&zq[n])[k];
                acc[n] = fma2(splat2(zc), w, acc[n]);
            }
        }
    }

    #pragma unroll
    for (int n = 0; n < 4; n++) {
        int v = vbase + n;
        if (v >= NN) break;
        float2 f = unpk(acc[n]);
        if (RELU_OUT) { f.x = fmaxf(f.x, 0.f); f.y = fmaxf(f.y, 0.f); }
        ((u64*)(h_out + (size_t)v * 64))[lane] = pk2(f.x, f.y);
    }
}

// ---------------- pooling + final linear ----------------
__global__ void pool_kernel(const float* __restrict__ h, const int* __restrict__ batch) {
    int gtid = blockIdx.x * blockDim.x + threadIdx.x;
    int v = gtid >> 5, lane = threadIdx.x & 31;
    if (v >= NN) return;
    int g = __ldg(&batch[v]);
    float2 val = *(const float2*)&h[(size_t)v * HH + 2 * lane];
    atomicAdd((float2*)&g_pool[g * HH + 2 * lane], val);
    if (lane == 0) atomicAdd(&g_cnt[g], 1);
}

__global__ void final_kernel(const float* __restrict__ lin_w,
                             const float* __restrict__ lin_b,
                             float* __restrict__ out) {
    int gtid = blockIdx.x * blockDim.x + threadIdx.x;
    int g = gtid >> 5, lane = threadIdx.x & 31;
    if (g >= BB) return;
    float s = g_pool[g * HH + lane] * __ldg(&lin_w[lane]) +
              g_pool[g * HH + 32 + lane] * __ldg(&lin_w[32 + lane]);
    #pragma unroll
    for (int o = 16; o; o >>= 1) s += __shfl_xor_sync(0xffffffffu, s, o);
    if (lane == 0) out[g] = s / fmaxf((float)g_cnt[g], 1.f) + lin_b[0];
}

// ---------------- launch ----------------
extern "C" void kernel_launch(void* const* d_in, const int* in_sizes, int n_in,
                              void* d_out, int out_size) {
    const float* x     = (const float*)d_in[0];
    const float* pos   = (const float*)d_in[1];
    const int*   ei    = (const int*)d_in[2];
    const int*   batch = (const int*)d_in[3];
    const float* W1f   = (const float*)d_in[4];
    const float* W1r   = (const float*)d_in[5];
    const float* b1    = (const float*)d_in[6];
    const float* W2    = (const float*)d_in[7];
    const float* b2    = (const float*)d_in[8];
    const float* lin_w = (const float*)d_in[9];
    const float* lin_b = (const float*)d_in[10];
    float* out = (float*)d_out;

    const int* src = ei;
    const int* dst = ei + EE;

    float *h0, *hA, *hB;
    cudaGetSymbolAddress((void**)&h0, g_h0);
    cudaGetSymbolAddress((void**)&hA, g_hA);
    cudaGetSymbolAddress((void**)&hB, g_hB);

    // smem (floats): W1 + W2 + 128 bias + 8 warps * (2 tiles of 4*64)
    const int smem32 = (32 * 64 + 4096 + 128 + 8 * 8 * 64) * 4;
    const int smem64 = (64 * 64 + 4096 + 128 + 8 * 8 * 64) * 4;
    cudaFuncSetAttribute(gin_layer<32, true>,  cudaFuncAttributeMaxDynamicSharedMemorySize, smem32);
    cudaFuncSetAttribute(gin_layer<64, true>,  cudaFuncAttributeMaxDynamicSharedMemorySize, smem64);
    cudaFuncSetAttribute(gin_layer<64, false>, cudaFuncAttributeMaxDynamicSharedMemorySize, smem64);

    init_kernel<<<(NN + 255) / 256, 256>>>();
    build_h0<<<(NN * 32 + 255) / 256, 256>>>(x, pos);
    hist_kernel<<<(EE + 255) / 256, 256>>>(dst);
    scanA_kernel<<<NSCAN_BLK, 1024>>>();
    scanB_kernel<<<1, 1>>>();
    scanC_kernel<<<NSCAN_BLK, 1024>>>();
    scatter_kernel<<<(EE + 255) / 256, 256>>>(src, dst);

    const int NB = (NN + 31) / 32;   // 32 nodes/block (8 warps x 4 nodes)

    gin_layer<32, true><<<NB, 256, smem32>>>(h0, hA, W1f, b1, W2, b2);

    float* cur = hA;
    float* nxt = hB;
    for (int l = 1; l < LL; l++) {
        const float* w1 = W1r + (size_t)(l - 1) * HH * HH;
        if (l < LL - 1)
            gin_layer<64, true><<<NB, 256, smem64>>>(cur, nxt, w1, b1 + l * HH,
                                                     W2 + (size_t)l * HH * HH, b2 + l * HH);
        else
            gin_layer<64, false><<<NB, 256, smem64>>>(cur, nxt, w1, b1 + l * HH,
                                                      W2 + (size_t)l * HH * HH, b2 + l * HH);
        float* t = cur; cur = nxt; nxt = t;
    }

    pool_kernel<<<(NN * 32 + 255) / 256, 256>>>(cur, batch);
    final_kernel<<<(BB * 32 + 255) / 256, 256>>>(lin_w, lin_b, out);
}

// round 4
// speedup vs baseline: 1.3769x; 1.1971x over previous
#include <cuda_runtime.h>

#define NN 50000
#define EE 800000
#define HH 64
#define BB 50
#define LL 7
#define NSCAN_BLK 49   // ceil(50000/1024)

// ---------------- scratch (device globals; no allocations) ----------------
__device__ float g_h0[NN * 32];
__device__ float g_hA[NN * 64];
__device__ float g_hB[NN * 64];
__device__ int   g_rowptr[NN + 1];    // raw (pre block-offset)
__device__ int   g_rowptr2[NN + 1];   // finalized
__device__ int   g_cursor[NN];
__device__ int   g_rank[EE];
__device__ int   g_csr[EE];
__device__ int   g_bsum[64];
__device__ float g_pool[BB * 64];
__device__ int   g_start[BB];         // persistent; rewritten identically each run
__device__ int   g_end[BB];

// ---------------- f32x2 helpers ----------------
typedef unsigned long long u64;
__device__ __forceinline__ u64 splat2(float x) {
    u64 r; asm("mov.b64 %0,{%1,%1};" : "=l"(r) : "f"(x)); return r;
}
__device__ __forceinline__ u64 fma2(u64 a, u64 b, u64 c) {
    u64 d; asm("fma.rn.f32x2 %0,%1,%2,%3;" : "=l"(d) : "l"(a), "l"(b), "l"(c)); return d;
}
__device__ __forceinline__ u64 add2(u64 a, u64 b) {
    u64 d; asm("add.rn.f32x2 %0,%1,%2;" : "=l"(d) : "l"(a), "l"(b)); return d;
}
__device__ __forceinline__ float2 unpk(u64 v) {
    float2 f; asm("mov.b64 {%0,%1},%2;" : "=f"(f.x), "=f"(f.y) : "l"(v)); return f;
}
__device__ __forceinline__ u64 pk2(float x, float y) {
    u64 r; asm("mov.b64 %0,{%1,%2};" : "=l"(r) : "f"(x), "f"(y)); return r;
}

// gather element traits: C=64 -> f32x2 per lane; C=32 -> scalar per lane
template <int C> struct GT;
template <> struct GT<64> {
    typedef u64 T;
    static __device__ __forceinline__ T zero() { return 0ULL; }
    static __device__ __forceinline__ T load(const float* h, int v, int lane) {
        return __ldg((const u64*)h + (size_t)v * 32 + lane);
    }
    static __device__ __forceinline__ T add(T a, T b) { return add2(a, b); }
};
template <> struct GT<32> {
    typedef float T;
    static __device__ __forceinline__ T zero() { return 0.f; }
    static __device__ __forceinline__ T load(const float* h, int v, int lane) {
        return __ldg(h + (size_t)v * 32 + lane);
    }
    static __device__ __forceinline__ T add(T a, T b) { return a + b; }
};

// ---------------- prologue ----------------
__global__ void fused_init(const float* __restrict__ x, const float* __restrict__ pos,
                           const int* __restrict__ batch) {
    int i = blockIdx.x * blockDim.x + threadIdx.x;
    if (i < NN * 32) {
        int v = i >> 5, c = i & 31;
        g_h0[i] = (c < 29) ? x[v * 29 + c] : pos[v * 3 + (c - 29)];
    }
    if (i < NN) {
        g_cursor[i] = 0;
        int bi = __ldg(&batch[i]);
        if (i == 0 || __ldg(&batch[i - 1]) != bi) g_start[bi] = i;
        if (i == NN - 1 || __ldg(&batch[i + 1]) != bi) g_end[bi] = i + 1;
    }
    if (i == 0) g_rowptr[0] = 0;
    if (i < BB * 64) g_pool[i] = 0.f;
}

__global__ void hist_kernel(const int* __restrict__ dst) {
    int e = blockIdx.x * blockDim.x + threadIdx.x;
    if (e < EE) g_rank[e] = atomicAdd(&g_cursor[dst[e]], 1);
}

__global__ void scanA_kernel() {
    __shared__ int wsum[32];
    int i = blockIdx.x * 1024 + threadIdx.x;
    int lane = threadIdx.x & 31, wid = threadIdx.x >> 5;
    int xx = (i < NN) ? g_cursor[i] : 0;
    #pragma unroll
    for (int o = 1; o < 32; o <<= 1) {
        int y = __shfl_up_sync(0xffffffffu, xx, o);
        if (lane >= o) xx += y;
    }
    if (lane == 31) wsum[wid] = xx;
    __syncthreads();
    if (wid == 0) {
        int s = wsum[lane];
        #pragma unroll
        for (int o = 1; o < 32; o <<= 1) {
            int y = __shfl_up_sync(0xffffffffu, s, o);
            if (lane >= o) s += y;
        }
        wsum[lane] = s;
    }
    __syncthreads();
    int incl = xx + (wid ? wsum[wid - 1] : 0);
    if (i < NN) g_rowptr[i + 1] = incl;
    if (threadIdx.x == 1023) g_bsum[blockIdx.x] = incl;
}

__global__ void scanB_kernel() {
    int s = 0;
    #pragma unroll
    for (int b = 0; b < NSCAN_BLK; b++) { int t = g_bsum[b]; g_bsum[b] = s; s += t; }
}

// scatter + rowptr finalize in one kernel (no scanC launch)
__global__ void scatter_fix(const int* __restrict__ src, const int* __restrict__ dst) {
    int e = blockIdx.x * blockDim.x + threadIdx.x;
    if (e <= NN) {
        int add = (e > 0) ? g_bsum[(e - 1) >> 10] : 0;
        g_rowptr2[e] = g_rowptr[e] + add;
    }
    if (e < EE) {
        int d = dst[e];
        int base = g_rowptr[d] + ((d > 0) ? g_bsum[(d - 1) >> 10] : 0);
        g_csr[base + g_rank[e]] = src[e];
    }
}

// ---------------- fused GIN layer ----------------
// 8 warps/block, 4 nodes/warp (12500 warps). Gather walks the warp's
// CONTIGUOUS csr span [rowptr2[vbase], rowptr2[vbase+4]) with 8/4/1-edge
// batches (8 independent LDG rows in flight) and warp-uniform boundary logic.
// GEMV: lane owns output pair (2l,2l+1), z broadcast via uniform LDS.128,
// weights LDS.64 lane-striped, f32x2 accumulation.
template <int C, bool RELU_OUT, bool POOL>
__global__ void __launch_bounds__(256) gin_layer(
    const float* __restrict__ h_in, float* __restrict__ h_out,
    const float* __restrict__ W1, const float* __restrict__ b1,
    const float* __restrict__ W2, const float* __restrict__ b2,
    const int* __restrict__ batch)
{
    typedef typename GT<C>::T T;
    extern __shared__ float smem[];
    float* sW1 = smem;                    // C*64
    float* sW2 = sW1 + C * 64;            // 64*64
    float* sb1 = sW2 + 4096;              // 64
    float* sb2 = sb1 + 64;                // 64
    float* warpbase = sb2 + 64 + (threadIdx.x >> 5) * 512;
    float* zt = warpbase;                 // 4 x C
    float* tt = warpbase + 256;           // 4 x 64

    for (int i = threadIdx.x; i < C * 64; i += 256) sW1[i] = W1[i];
    for (int i = threadIdx.x; i < 64 * 64; i += 256) sW2[i] = W2[i];
    if (threadIdx.x < 64) { sb1[threadIdx.x] = b1[threadIdx.x]; sb2[threadIdx.x] = b2[threadIdx.x]; }
    __syncthreads();

    const int lane  = threadIdx.x & 31;
    const int vbase = (blockIdx.x * 8 + (threadIdx.x >> 5)) * 4;

    // ---- gather over contiguous span ----
    {
        int v0c = vbase;     if (v0c > NN) v0c = NN;
        int v4c = vbase + 4; if (v4c > NN) v4c = NN;
        int e    = __ldg(&g_rowptr2[v0c]);
        int eend = __ldg(&g_rowptr2[v4c]);
        int n = 0;
        int bnext = vbase + 1; if (bnext > NN) bnext = NN;
        int b = __ldg(&g_rowptr2[bnext]);
        T zc = (vbase < NN) ? GT<C>::load(h_in, vbase, lane) : GT<C>::zero();

        while (e < eend) {
            if (e + 8 <= b) {
                int s0 = __ldg(&g_csr[e]);
                int s1 = __ldg(&g_csr[e + 1]);
                int s2 = __ldg(&g_csr[e + 2]);
                int s3 = __ldg(&g_csr[e + 3]);
                int s4 = __ldg(&g_csr[e + 4]);
                int s5 = __ldg(&g_csr[e + 5]);
                int s6 = __ldg(&g_csr[e + 6]);
                int s7 = __ldg(&g_csr[e + 7]);
                T a0 = GT<C>::load(h_in, s0, lane);
                T a1 = GT<C>::load(h_in, s1, lane);
                T a2 = GT<C>::load(h_in, s2, lane);
                T a3 = GT<C>::load(h_in, s3, lane);
                T a4 = GT<C>::load(h_in, s4, lane);
                T a5 = GT<C>::load(h_in, s5, lane);
                T a6 = GT<C>::load(h_in, s6, lane);
                T a7 = GT<C>::load(h_in, s7, lane);
                T s = GT<C>::add(GT<C>::add(GT<C>::add(a0, a1), GT<C>::add(a2, a3)),
                                 GT<C>::add(GT<C>::add(a4, a5), GT<C>::add(a6, a7)));
                zc = GT<C>::add(zc, s);
                e += 8;
            } else if (e + 4 <= b) {
                int s0 = __ldg(&g_csr[e]);
                int s1 = __ldg(&g_csr[e + 1]);
                int s2 = __ldg(&g_csr[e + 2]);
                int s3 = __ldg(&g_csr[e + 3]);
                T a0 = GT<C>::load(h_in, s0, lane);
                T a1 = GT<C>::load(h_in, s1, lane);
                T a2 = GT<C>::load(h_in, s2, lane);
                T a3 = GT<C>::load(h_in, s3, lane);
                zc = GT<C>::add(zc, GT<C>::add(GT<C>::add(a0, a1), GT<C>::add(a2, a3)));
                e += 4;
            } else if (e < b) {
                int s0 = __ldg(&g_csr[e]);
                zc = GT<C>::add(zc, GT<C>::load(h_in, s0, lane));
                e += 1;
            } else {
                // flush node n, move to next
                ((T*)zt)[n * 32 + lane] = zc;
                n++;
                int v = vbase + n;
                zc = (v < NN) ? GT<C>::load(h_in, v, lane) : GT<C>::zero();
                int bi = v + 1; if (bi > NN) bi = NN;
                b = __ldg(&g_rowptr2[bi]);
            }
        }
        // flush remaining nodes
        while (true) {
            ((T*)zt)[n * 32 + lane] = zc;
            if (++n > 3) break;
            int v = vbase + n;
            zc = (v < NN) ? GT<C>::load(h_in, v, lane) : GT<C>::zero();
        }
    }
    __syncwarp();

    // ---- GEMV1: t = relu(z @ W1 + b1) ----
    u64 acc[4];
    {
        u64 bias = ((const u64*)sb1)[lane];
        #pragma unroll
        for (int n = 0; n < 4; n++) acc[n] = bias;
    }
    for (int c4 = 0; c4 < C; c4 += 4) {
        float4 zq[4];
        #pragma unroll
        for (int n = 0; n < 4; n++)
            zq[n] = *(const float4*)&zt[n * C + c4];   // uniform broadcast
        #pragma unroll
        for (int k = 0; k < 4; k++) {
            u64 w = ((const u64*)(sW1 + (c4 + k) * 64))[lane];
            #pragma unroll
            for (int n = 0; n < 4; n++) {
                float zc = ((const float*)&zq[n])[k];
                acc[n] = fma2(splat2(zc), w, acc[n]);
            }
        }
    }
    #pragma unroll
    for (int n = 0; n < 4; n++) {
        float2 f = unpk(acc[n]);
        ((u64*)tt)[n * 32 + lane] = pk2(fmaxf(f.x, 0.f), fmaxf(f.y, 0.f));
    }
    __syncwarp();

    // ---- GEMV2: o = t @ W2 + b2 ----
    {
        u64 bias = ((const u64*)sb2)[lane];
        #pragma unroll
        for (int n = 0; n < 4; n++) acc[n] = bias;
    }
    for (int c4 = 0; c4 < 64; c4 += 4) {
        float4 zq[4];
        #pragma unroll
        for (int n = 0; n < 4; n++)
            zq[n] = *(const float4*)&tt[n * 64 + c4];
        #pragma unroll
        for (int k = 0; k < 4; k++) {
            u64 w = ((const u64*)(sW2 + (c4 + k) * 64))[lane];
            #pragma unroll
            for (int n = 0; n < 4; n++) {
                float zc = ((const float*)&zq[n])[k];
                acc[n] = fma2(splat2(zc), w, acc[n]);
            }
        }
    }

    if (POOL) {
        // mean-pool contribution (batch is sorted; 4 consecutive nodes usually same graph)
        if (vbase + 3 < NN) {
            int ga = __ldg(&batch[vbase]);
            int gb = __ldg(&batch[vbase + 3]);
            if (ga == gb) {
                u64 s = add2(add2(acc[0], acc[1]), add2(acc[2], acc[3]));
                float2 f = unpk(s);
                atomicAdd((float2*)&g_pool[ga * 64 + 2 * lane], f);
                return;
            }
        }
        #pragma unroll
        for (int n = 0; n < 4; n++) {
            int v = vbase + n;
            if (v >= NN) break;
            int g = __ldg(&batch[v]);
            float2 f = unpk(acc[n]);
            atomicAdd((float2*)&g_pool[g * 64 + 2 * lane], f);
        }
    } else {
        #pragma unroll
        for (int n = 0; n < 4; n++) {
            int v = vbase + n;
            if (v >= NN) break;
            float2 f = unpk(acc[n]);
            if (RELU_OUT) { f.x = fmaxf(f.x, 0.f); f.y = fmaxf(f.y, 0.f); }
            ((u64*)(h_out + (size_t)v * 64))[lane] = pk2(f.x, f.y);
        }
    }
}

// ---------------- final linear ----------------
__global__ void final_kernel(const float* __restrict__ lin_w,
                             const float* __restrict__ lin_b,
                             float* __restrict__ out) {
    int gtid = blockIdx.x * blockDim.x + threadIdx.x;
    int g = gtid >> 5, lane = threadIdx.x & 31;
    if (g >= BB) return;
    float s = g_pool[g * 64 + lane] * __ldg(&lin_w[lane]) +
              g_pool[g * 64 + 32 + lane] * __ldg(&lin_w[32 + lane]);
    #pragma unroll
    for (int o = 16; o; o >>= 1) s += __shfl_xor_sync(0xffffffffu, s, o);
    if (lane == 0) {
        float cnt = (float)(g_end[g] - g_start[g]);
        out[g] = s / fmaxf(cnt, 1.f) + lin_b[0];
    }
}

// ---------------- launch ----------------
extern "C" void kernel_launch(void* const* d_in, const int* in_sizes, int n_in,
                              void* d_out, int out_size) {
    const float* x     = (const float*)d_in[0];
    const float* pos   = (const float*)d_in[1];
    const int*   ei    = (const int*)d_in[2];
    const int*   batch = (const int*)d_in[3];
    const float* W1f   = (const float*)d_in[4];
    const float* W1r   = (const float*)d_in[5];
    const float* b1    = (const float*)d_in[6];
    const float* W2    = (const float*)d_in[7];
    const float* b2    = (const float*)d_in[8];
    const float* lin_w = (const float*)d_in[9];
    const float* lin_b = (const float*)d_in[10];
    float* out = (float*)d_out;

    const int* src = ei;
    const int* dst = ei + EE;

    float *h0, *hA, *hB;
    cudaGetSymbolAddress((void**)&h0, g_h0);
    cudaGetSymbolAddress((void**)&hA, g_hA);
    cudaGetSymbolAddress((void**)&hB, g_hB);

    // smem (floats): W1 + W2 + 128 bias + 8 warps * 512
    const int smem32 = (32 * 64 + 4096 + 128 + 8 * 512) * 4;
    const int smem64 = (64 * 64 + 4096 + 128 + 8 * 512) * 4;
    cudaFuncSetAttribute((const void*)gin_layer<32, true,  false>, cudaFuncAttributeMaxDynamicSharedMemorySize, smem32);
    cudaFuncSetAttribute((const void*)gin_layer<64, true,  false>, cudaFuncAttributeMaxDynamicSharedMemorySize, smem64);
    cudaFuncSetAttribute((const void*)gin_layer<64, false, true>,  cudaFuncAttributeMaxDynamicSharedMemorySize, smem64);

    // 5 prologue launches (ncu -s 5 -c 1 then captures the first gin_layer)
    fused_init<<<(NN * 32 + 255) / 256, 256>>>(x, pos, batch);
    hist_kernel<<<(EE + 255) / 256, 256>>>(dst);
    scanA_kernel<<<NSCAN_BLK, 1024>>>();
    scanB_kernel<<<1, 1>>>();
    scatter_fix<<<(EE + 255) / 256, 256>>>(src, dst);

    const int NB = (NN + 31) / 32;   // 32 nodes/block

    gin_layer<32, true, false><<<NB, 256, smem32>>>(h0, hA, W1f, b1, W2, b2, batch);

    float* cur = hA;
    float* nxt = hB;
    for (int l = 1; l < LL; l++) {
        const float* w1 = W1r + (size_t)(l - 1) * HH * HH;
        if (l < LL - 1) {
            gin_layer<64, true, false><<<NB, 256, smem64>>>(cur, nxt, w1, b1 + l * HH,
                                                            W2 + (size_t)l * HH * HH, b2 + l * HH, batch);
            float* t = cur; cur = nxt; nxt = t;
        } else {
            gin_layer<64, false, true><<<NB, 256, smem64>>>(cur, nxt, w1, b1 + l * HH,
                                                            W2 + (size_t)l * HH * HH, b2 + l * HH, batch);
        }
    }

    final_kernel<<<(BB * 32 + 255) / 256, 256>>>(lin_w, lin_b, out);
}

// round 5
// speedup vs baseline: 1.3790x; 1.0015x over previous
#include <cuda_runtime.h>

#define NN 50000
#define EE 800000
#define HH 64
#define BB 50
#define LL 7
#define NSCAN_BLK 49   // ceil(50000/1024)

// ---------------- scratch (device globals; no allocations) ----------------
// NOTE: g_cursor must be zero at entry to each kernel_launch call. It is
// zero-initialized at load, and scatter_fix re-zeroes it every call, so the
// invariant holds across correctness run + every graph replay.
__device__ float g_h0[NN * 32];
__device__ float g_hA[NN * 64];
__device__ float g_hB[NN * 64];
__device__ int   g_rowptr[NN + 1];    // raw (pre block-offset)
__device__ int   g_rowptr2[NN + 1];   // finalized
__device__ int   g_cursor[NN];
__device__ int   g_rank[EE];
__device__ int   g_csr[EE];
__device__ int   g_bsum[64];
__device__ float g_pool[BB * 64];
__device__ int   g_start[BB];
__device__ int   g_end[BB];

// ---------------- f32x2 helpers ----------------
typedef unsigned long long u64;
__device__ __forceinline__ u64 splat2(float x) {
    u64 r; asm("mov.b64 %0,{%1,%1};" : "=l"(r) : "f"(x)); return r;
}
__device__ __forceinline__ u64 fma2(u64 a, u64 b, u64 c) {
    u64 d; asm("fma.rn.f32x2 %0,%1,%2,%3;" : "=l"(d) : "l"(a), "l"(b), "l"(c)); return d;
}
__device__ __forceinline__ u64 add2(u64 a, u64 b) {
    u64 d; asm("add.rn.f32x2 %0,%1,%2;" : "=l"(d) : "l"(a), "l"(b)); return d;
}
__device__ __forceinline__ float2 unpk(u64 v) {
    float2 f; asm("mov.b64 {%0,%1},%2;" : "=f"(f.x), "=f"(f.y) : "l"(v)); return f;
}
__device__ __forceinline__ u64 pk2(float x, float y) {
    u64 r; asm("mov.b64 %0,{%1,%2};" : "=l"(r) : "f"(x), "f"(y)); return r;
}

// gather element traits
template <int C> struct GT;
template <> struct GT<64> {
    typedef u64 T;
    static __device__ __forceinline__ T zero() { return 0ULL; }
    static __device__ __forceinline__ T load(const float* h, int v, int lane) {
        return __ldg((const u64*)h + (size_t)v * 32 + lane);
    }
    static __device__ __forceinline__ T add(T a, T b) { return add2(a, b); }
};
template <> struct GT<32> {
    typedef float T;
    static __device__ __forceinline__ T zero() { return 0.f; }
    static __device__ __forceinline__ T load(const float* h, int v, int lane) {
        return __ldg(h + (size_t)v * 32 + lane);
    }
    static __device__ __forceinline__ T add(T a, T b) { return a + b; }
};

// ---------------- launch 1: init + h0 + degree histogram ----------------
__global__ void fused_init(const float* __restrict__ x, const float* __restrict__ pos,
                           const int* __restrict__ batch, const int* __restrict__ dst,
                           const int* __restrict__ src) {
    int i = blockIdx.x * blockDim.x + threadIdx.x;
    if (i < NN * 32) {
        int v = i >> 5, c = i & 31;
        g_h0[i] = (c < 29) ? x[v * 29 + c] : pos[v * 3 + (c - 29)];
    }
    if (i < EE) {
        // g_cursor is zero at entry (see note at declarations)
        g_rank[i] = atomicAdd(&g_cursor[dst[i]], 1);
    }
    if (i < NN) {
        int bi = __ldg(&batch[i]);
        if (i == 0 || __ldg(&batch[i - 1]) != bi) g_start[bi] = i;
        if (i == NN - 1 || __ldg(&batch[i + 1]) != bi) g_end[bi] = i + 1;
    }
    if (i == 0) g_rowptr[0] = 0;
    if (i < BB * 64) g_pool[i] = 0.f;
}

// ---------------- launch 2: per-block scan of degrees ----------------
__global__ void scanA_kernel() {
    __shared__ int wsum[32];
    int i = blockIdx.x * 1024 + threadIdx.x;
    int lane = threadIdx.x & 31, wid = threadIdx.x >> 5;
    int xx = (i < NN) ? g_cursor[i] : 0;
    #pragma unroll
    for (int o = 1; o < 32; o <<= 1) {
        int y = __shfl_up_sync(0xffffffffu, xx, o);
        if (lane >= o) xx += y;
    }
    if (lane == 31) wsum[wid] = xx;
    __syncthreads();
    if (wid == 0) {
        int s = wsum[lane];
        #pragma unroll
        for (int o = 1; o < 32; o <<= 1) {
            int y = __shfl_up_sync(0xffffffffu, s, o);
            if (lane >= o) s += y;
        }
        wsum[lane] = s;
    }
    __syncthreads();
    int incl = xx + (wid ? wsum[wid - 1] : 0);
    if (i < NN) g_rowptr[i + 1] = incl;
    if (threadIdx.x == 1023) g_bsum[blockIdx.x] = incl;
}

// ---------------- launch 3: scatter + rowptr finalize + cursor re-zero ----------------
__global__ void scatter_fix(const int* __restrict__ src, const int* __restrict__ dst) {
    __shared__ int sb[NSCAN_BLK + 1];
    // replicate the tiny 49-element exclusive scan per block
    if (threadIdx.x < NSCAN_BLK) sb[threadIdx.x + 1] = g_bsum[threadIdx.x];
    __syncthreads();
    if (threadIdx.x == 0) {
        int run = 0;
        #pragma unroll
        for (int k = 0; k < NSCAN_BLK; k++) { int t = sb[k + 1]; sb[k] = run; run += t; }
    }
    __syncthreads();

    int e = blockIdx.x * blockDim.x + threadIdx.x;
    if (e <= NN) {
        int add = (e > 0) ? sb[(e - 1) >> 10] : 0;
        g_rowptr2[e] = g_rowptr[e] + add;
    }
    if (e < EE) {
        int d = dst[e];
        int base = g_rowptr[d] + ((d > 0) ? sb[(d - 1) >> 10] : 0);
        g_csr[base + g_rank[e]] = src[e];
    }
    if (e < NN) g_cursor[e] = 0;   // restore invariant for next call
}

// ---------------- fused GIN layer ----------------
// 8 warps/block, 4 nodes/warp. Two-phase gather:
//   A) lanes cooperatively copy the warp's contiguous csr span into SMEM
//      (coalesced LDG.32, no dependent chains)
//   B) row gathers take addresses from SMEM (LDS) -> only loop-carried dep is
//      the accumulator add; row LDGs pipeline freely -> L2-BW-bound.
// GEMV: lane owns output pair (2l,2l+1); z uniform-broadcast LDS.128, weights
// LDS.64 lane-striped, f32x2 accumulation.
template <int C, bool RELU_OUT, bool POOL>
__global__ void __launch_bounds__(256) gin_layer(
    const float* __restrict__ h_in, float* __restrict__ h_out,
    const float* __restrict__ W1, const float* __restrict__ b1,
    const float* __restrict__ W2, const float* __restrict__ b2,
    const int* __restrict__ batch)
{
    typedef typename GT<C>::T T;
    extern __shared__ float smem[];
    float* sW1 = smem;                    // C*64
    float* sW2 = sW1 + C * 64;            // 64*64
    float* sb1 = sW2 + 4096;              // 64
    float* sb2 = sb1 + 64;                // 64
    float* warpbase = sb2 + 64 + (threadIdx.x >> 5) * 512;
    float* zt = warpbase;                 // [0,256): z tile (4 x C)
    int*   sidx = (int*)(warpbase + 256); // [256,512): csr span cache (256 ints)
    float* tt = warpbase + 256;           // t tile reuses sidx region after gather

    for (int i = threadIdx.x; i < C * 64; i += 256) sW1[i] = W1[i];
    for (int i = threadIdx.x; i < 64 * 64; i += 256) sW2[i] = W2[i];
    if (threadIdx.x < 64) { sb1[threadIdx.x] = b1[threadIdx.x]; sb2[threadIdx.x] = b2[threadIdx.x]; }
    __syncthreads();

    const int lane  = threadIdx.x & 31;
    const int vbase = (blockIdx.x * 8 + (threadIdx.x >> 5)) * 4;

    // rowptrs for this warp's 4 nodes (clamped)
    int rp[5];
    #pragma unroll
    for (int k = 0; k < 5; k++) {
        int v = vbase + k; if (v > NN) v = NN;
        rp[k] = __ldg(&g_rowptr2[v]);
    }
    const int e0 = rp[0];
    const int span = rp[4] - e0;
    const int cap = (span < 256) ? span : 256;

    // ---- phase A: cache csr span in SMEM (coalesced, chain-free) ----
    for (int k = lane; k < cap; k += 32) sidx[k] = __ldg(&g_csr[e0 + k]);
    __syncwarp();

    // ---- phase B: per-node row gathers, addresses from SMEM ----
    #pragma unroll
    for (int n = 0; n < 4; n++) {
        int v = vbase + n;
        if (v >= NN) break;
        T z = GT<C>::load(h_in, v, lane);
        int b0 = rp[n] - e0, b1e = rp[n + 1] - e0;
        if (b1e <= cap) {
            int k = b0;
            for (; k + 8 <= b1e; k += 8) {
                int s0 = sidx[k],     s1 = sidx[k + 1];
                int s2 = sidx[k + 2], s3 = sidx[k + 3];
                int s4 = sidx[k + 4], s5 = sidx[k + 5];
                int s6 = sidx[k + 6], s7 = sidx[k + 7];
                T a0 = GT<C>::load(h_in, s0, lane);
                T a1 = GT<C>::load(h_in, s1, lane);
                T a2 = GT<C>::load(h_in, s2, lane);
                T a3 = GT<C>::load(h_in, s3, lane);
                T a4 = GT<C>::load(h_in, s4, lane);
                T a5 = GT<C>::load(h_in, s5, lane);
                T a6 = GT<C>::load(h_in, s6, lane);
                T a7 = GT<C>::load(h_in, s7, lane);
                z = GT<C>::add(z,
                    GT<C>::add(GT<C>::add(GT<C>::add(a0, a1), GT<C>::add(a2, a3)),
                               GT<C>::add(GT<C>::add(a4, a5), GT<C>::add(a6, a7))));
            }
            for (; k < b1e; k++)
                z = GT<C>::add(z, GT<C>::load(h_in, sidx[k], lane));
        } else {
            // rare overflow: direct global walk
            for (int k = b0; k < b1e; k++)
                z = GT<C>::add(z, GT<C>::load(h_in, __ldg(&g_csr[e0 + k]), lane));
        }
        ((T*)zt)[n * 32 + lane] = z;
    }
    __syncwarp();

    // ---- GEMV1: t = relu(z @ W1 + b1) ----
    u64 acc[4];
    {
        u64 bias = ((const u64*)sb1)[lane];
        #pragma unroll
        for (int n = 0; n < 4; n++) acc[n] = bias;
    }
    for (int c4 = 0; c4 < C; c4 += 4) {
        float4 zq[4];
        #pragma unroll
        for (int n = 0; n < 4; n++)
            zq[n] = *(const float4*)&zt[n * C + c4];   // uniform broadcast
        #pragma unroll
        for (int k = 0; k < 4; k++) {
            u64 w = ((const u64*)(sW1 + (c4 + k) * 64))[lane];
            #pragma unroll
            for (int n = 0; n < 4; n++) {
                float zc = ((const float*)&zq[n])[k];
                acc[n] = fma2(splat2(zc), w, acc[n]);
            }
        }
    }
    __syncwarp();   // sidx reads done before tt overwrites (same region)
    #pragma unroll
    for (int n = 0; n < 4; n++) {
        float2 f = unpk(acc[n]);
        ((u64*)tt)[n * 32 + lane] = pk2(fmaxf(f.x, 0.f), fmaxf(f.y, 0.f));
    }
    __syncwarp();

    // ---- GEMV2: o = t @ W2 + b2 ----
    {
        u64 bias = ((const u64*)sb2)[lane];
        #pragma unroll
        for (int n = 0; n < 4; n++) acc[n] = bias;
    }
    for (int c4 = 0; c4 < 64; c4 += 4) {
        float4 zq[4];
        #pragma unroll
        for (int n = 0; n < 4; n++)
            zq[n] = *(const float4*)&tt[n * 64 + c4];
        #pragma unroll
        for (int k = 0; k < 4; k++) {
            u64 w = ((const u64*)(sW2 + (c4 + k) * 64))[lane];
            #pragma unroll
            for (int n = 0; n < 4; n++) {
                float zc = ((const float*)&zq[n])[k];
                acc[n] = fma2(splat2(zc), w, acc[n]);
            }
        }
    }

    if (POOL) {
        if (vbase + 3 < NN) {
            int ga = __ldg(&batch[vbase]);
            int gb = __ldg(&batch[vbase + 3]);
            if (ga == gb) {
                u64 s = add2(add2(acc[0], acc[1]), add2(acc[2], acc[3]));
                float2 f = unpk(s);
                atomicAdd((float2*)&g_pool[ga * 64 + 2 * lane], f);
                return;
            }
        }
        #pragma unroll
        for (int n = 0; n < 4; n++) {
            int v = vbase + n;
            if (v >= NN) break;
            int g = __ldg(&batch[v]);
            float2 f = unpk(acc[n]);
            atomicAdd((float2*)&g_pool[g * 64 + 2 * lane], f);
        }
    } else {
        #pragma unroll
        for (int n = 0; n < 4; n++) {
            int v = vbase + n;
            if (v >= NN) break;
            float2 f = unpk(acc[n]);
            if (RELU_OUT) { f.x = fmaxf(f.x, 0.f); f.y = fmaxf(f.y, 0.f); }
            ((u64*)(h_out + (size_t)v * 64))[lane] = pk2(f.x, f.y);
        }
    }
}

// ---------------- final linear ----------------
__global__ void final_kernel(const float* __restrict__ lin_w,
                             const float* __restrict__ lin_b,
                             float* __restrict__ out) {
    int gtid = blockIdx.x * blockDim.x + threadIdx.x;
    int g = gtid >> 5, lane = threadIdx.x & 31;
    if (g >= BB) return;
    float s = g_pool[g * 64 + lane] * __ldg(&lin_w[lane]) +
              g_pool[g * 64 + 32 + lane] * __ldg(&lin_w[32 + lane]);
    #pragma unroll
    for (int o = 16; o; o >>= 1) s += __shfl_xor_sync(0xffffffffu, s, o);
    if (lane == 0) {
        float cnt = (float)(g_end[g] - g_start[g]);
        out[g] = s / fmaxf(cnt, 1.f) + lin_b[0];
    }
}

// ---------------- launch ----------------
extern "C" void kernel_launch(void* const* d_in, const int* in_sizes, int n_in,
                              void* d_out, int out_size) {
    const float* x     = (const float*)d_in[0];
    const float* pos   = (const float*)d_in[1];
    const int*   ei    = (const int*)d_in[2];
    const int*   batch = (const int*)d_in[3];
    const float* W1f   = (const float*)d_in[4];
    const float* W1r   = (const float*)d_in[5];
    const float* b1    = (const float*)d_in[6];
    const float* W2    = (const float*)d_in[7];
    const float* b2    = (const float*)d_in[8];
    const float* lin_w = (const float*)d_in[9];
    const float* lin_b = (const float*)d_in[10];
    float* out = (float*)d_out;

    const int* src = ei;
    const int* dst = ei + EE;

    float *h0, *hA, *hB;
    cudaGetSymbolAddress((void**)&h0, g_h0);
    cudaGetSymbolAddress((void**)&hA, g_hA);
    cudaGetSymbolAddress((void**)&hB, g_hB);

    const int smem32 = (32 * 64 + 4096 + 128 + 8 * 512) * 4;
    const int smem64 = (64 * 64 + 4096 + 128 + 8 * 512) * 4;
    cudaFuncSetAttribute((const void*)gin_layer<32, true,  false>, cudaFuncAttributeMaxDynamicSharedMemorySize, smem32);
    cudaFuncSetAttribute((const void*)gin_layer<64, true,  false>, cudaFuncAttributeMaxDynamicSharedMemorySize, smem64);
    cudaFuncSetAttribute((const void*)gin_layer<64, false, true>,  cudaFuncAttributeMaxDynamicSharedMemorySize, smem64);

    // 3 prologue launches -> launch #4 is the first gin_layer (profiled)
    fused_init<<<(NN * 32 + 255) / 256, 256>>>(x, pos, batch, dst, src);
    scanA_kernel<<<NSCAN_BLK, 1024>>>();
    scatter_fix<<<(EE + 255) / 256, 256>>>(src, dst);

    const int NB = (NN + 31) / 32;   // 32 nodes/block

    gin_layer<32, true, false><<<NB, 256, smem32>>>(h0, hA, W1f, b1, W2, b2, batch);

    float* cur = hA;
    float* nxt = hB;
    for (int l = 1; l < LL; l++) {
        const float* w1 = W1r + (size_t)(l - 1) * HH * HH;
        if (l < LL - 1) {
            gin_layer<64, true, false><<<NB, 256, smem64>>>(cur, nxt, w1, b1 + l * HH,
                                                            W2 + (size_t)l * HH * HH, b2 + l * HH, batch);
            float* t = cur; cur = nxt; nxt = t;
        } else {
            gin_layer<64, false, true><<<NB, 256, smem64>>>(cur, nxt, w1, b1 + l * HH,
                                                            W2 + (size_t)l * HH * HH, b2 + l * HH, batch);
        }
    }

    final_kernel<<<(BB * 32 + 255) / 256, 256>>>(lin_w, lin_b, out);
}

// round 6
// speedup vs baseline: 1.8557x; 1.3457x over previous
#include <cuda_runtime.h>

#define NN 50000
#define EE 800000
#define HH 64
#define BB 50
#define LL 7
#define NSCAN_BLK 49   // ceil(50000/1024)

// ---------------- scratch (device globals; no allocations) ----------------
// NOTE: g_cursor must be zero at entry to each kernel_launch call. It is
// zero-initialized at load, and scatter_fix re-zeroes it every call, so the
// invariant holds across correctness run + every graph replay.
__device__ float g_h0[NN * 32];
__device__ float g_hA[NN * 64];
__device__ float g_hB[NN * 64];
__device__ int   g_rowptr[NN + 1];    // raw (pre block-offset)
__device__ int   g_rowptr2[NN + 1];   // finalized
__device__ int   g_cursor[NN];
__device__ int   g_rank[EE];
__device__ int   g_csr[EE];
__device__ int   g_bsum[64];
__device__ float g_pool[BB * 64];
__device__ int   g_start[BB];
__device__ int   g_end[BB];

// ---------------- f32x2 helpers ----------------
typedef unsigned long long u64;
__device__ __forceinline__ u64 splat2(float x) {
    u64 r; asm("mov.b64 %0,{%1,%1};" : "=l"(r) : "f"(x)); return r;
}
__device__ __forceinline__ u64 fma2(u64 a, u64 b, u64 c) {
    u64 d; asm("fma.rn.f32x2 %0,%1,%2,%3;" : "=l"(d) : "l"(a), "l"(b), "l"(c)); return d;
}
__device__ __forceinline__ u64 add2(u64 a, u64 b) {
    u64 d; asm("add.rn.f32x2 %0,%1,%2;" : "=l"(d) : "l"(a), "l"(b)); return d;
}
__device__ __forceinline__ float2 unpk(u64 v) {
    float2 f; asm("mov.b64 {%0,%1},%2;" : "=f"(f.x), "=f"(f.y) : "l"(v)); return f;
}
__device__ __forceinline__ u64 pk2(float x, float y) {
    u64 r; asm("mov.b64 %0,{%1,%2};" : "=l"(r) : "f"(x), "f"(y)); return r;
}

// gather element traits
template <int C> struct GT;
template <> struct GT<64> {
    typedef u64 T;
    static __device__ __forceinline__ T zero() { return 0ULL; }
    static __device__ __forceinline__ T load(const float* h, int v, int lane) {
        return __ldg((const u64*)h + (size_t)v * 32 + lane);
    }
    static __device__ __forceinline__ T add(T a, T b) { return add2(a, b); }
};
template <> struct GT<32> {
    typedef float T;
    static __device__ __forceinline__ T zero() { return 0.f; }
    static __device__ __forceinline__ T load(const float* h, int v, int lane) {
        return __ldg(h + (size_t)v * 32 + lane);
    }
    static __device__ __forceinline__ T add(T a, T b) { return a + b; }
};

// ---------------- launch 1: init + h0 + degree histogram ----------------
__global__ void fused_init(const float* __restrict__ x, const float* __restrict__ pos,
                           const int* __restrict__ batch, const int* __restrict__ dst,
                           const int* __restrict__ src) {
    int i = blockIdx.x * blockDim.x + threadIdx.x;
    if (i < NN * 32) {
        int v = i >> 5, c = i & 31;
        g_h0[i] = (c < 29) ? x[v * 29 + c] : pos[v * 3 + (c - 29)];
    }
    if (i < EE) {
        g_rank[i] = atomicAdd(&g_cursor[dst[i]], 1);
    }
    if (i < NN) {
        int bi = __ldg(&batch[i]);
        if (i == 0 || __ldg(&batch[i - 1]) != bi) g_start[bi] = i;
        if (i == NN - 1 || __ldg(&batch[i + 1]) != bi) g_end[bi] = i + 1;
    }
    if (i == 0) g_rowptr[0] = 0;
    if (i < BB * 64) g_pool[i] = 0.f;
}

// ---------------- launch 2: per-block scan of degrees ----------------
__global__ void scanA_kernel() {
    __shared__ int wsum[32];
    int i = blockIdx.x * 1024 + threadIdx.x;
    int lane = threadIdx.x & 31, wid = threadIdx.x >> 5;
    int xx = (i < NN) ? g_cursor[i] : 0;
    #pragma unroll
    for (int o = 1; o < 32; o <<= 1) {
        int y = __shfl_up_sync(0xffffffffu, xx, o);
        if (lane >= o) xx += y;
    }
    if (lane == 31) wsum[wid] = xx;
    __syncthreads();
    if (wid == 0) {
        int s = wsum[lane];
        #pragma unroll
        for (int o = 1; o < 32; o <<= 1) {
            int y = __shfl_up_sync(0xffffffffu, s, o);
            if (lane >= o) s += y;
        }
        wsum[lane] = s;
    }
    __syncthreads();
    int incl = xx + (wid ? wsum[wid - 1] : 0);
    if (i < NN) g_rowptr[i + 1] = incl;
    if (threadIdx.x == 1023) g_bsum[blockIdx.x] = incl;
}

// ---------------- launch 3: scatter + rowptr finalize + cursor re-zero ----------------
__global__ void scatter_fix(const int* __restrict__ src, const int* __restrict__ dst) {
    __shared__ int sb[NSCAN_BLK + 1];
    if (threadIdx.x < NSCAN_BLK) sb[threadIdx.x + 1] = g_bsum[threadIdx.x];
    __syncthreads();
    if (threadIdx.x == 0) {
        int run = 0;
        #pragma unroll
        for (int k = 0; k < NSCAN_BLK; k++) { int t = sb[k + 1]; sb[k] = run; run += t; }
    }
    __syncthreads();

    int e = blockIdx.x * blockDim.x + threadIdx.x;
    if (e <= NN) {
        int add = (e > 0) ? sb[(e - 1) >> 10] : 0;
        g_rowptr2[e] = g_rowptr[e] + add;
    }
    if (e < EE) {
        int d = dst[e];
        int base = g_rowptr[d] + ((d > 0) ? sb[(d - 1) >> 10] : 0);
        g_csr[base + g_rank[e]] = src[e];
    }
    if (e < NN) g_cursor[e] = 0;
}

// ---------------- fused GIN layer ----------------
// 16 warps/block (512 thr, one shared weight copy -> 3 blocks/SM, 48 warps/SM),
// 4 nodes/warp (12512 warps chip-wide). Two-phase gather with 16-deep load
// batching; GEMV with f32x2, lane owns output pair (2l,2l+1).
template <int C, bool RELU_OUT, bool POOL>
__global__ void __launch_bounds__(512) gin_layer(
    const float* __restrict__ h_in, float* __restrict__ h_out,
    const float* __restrict__ W1, const float* __restrict__ b1,
    const float* __restrict__ W2, const float* __restrict__ b2,
    const int* __restrict__ batch)
{
    typedef typename GT<C>::T T;
    extern __shared__ float smem[];
    float* sW1 = smem;                    // C*64
    float* sW2 = sW1 + C * 64;            // 64*64
    float* sb1 = sW2 + 4096;              // 64
    float* sb2 = sb1 + 64;                // 64
    float* warpbase = sb2 + 64 + (threadIdx.x >> 5) * 512;
    float* zt = warpbase;                 // [0,256): z tile (4 x C)
    int*   sidx = (int*)(warpbase + 256); // [256,512): csr span cache (256 ints)
    float* tt = warpbase + 256;           // t tile reuses sidx region after gather

    for (int i = threadIdx.x; i < C * 64; i += 512) sW1[i] = W1[i];
    for (int i = threadIdx.x; i < 64 * 64; i += 512) sW2[i] = W2[i];
    if (threadIdx.x < 64) { sb1[threadIdx.x] = b1[threadIdx.x]; sb2[threadIdx.x] = b2[threadIdx.x]; }
    __syncthreads();

    const int lane  = threadIdx.x & 31;
    const int vbase = (blockIdx.x * 16 + (threadIdx.x >> 5)) * 4;

    // rowptrs for this warp's 4 nodes (clamped)
    int rp[5];
    #pragma unroll
    for (int k = 0; k < 5; k++) {
        int v = vbase + k; if (v > NN) v = NN;
        rp[k] = __ldg(&g_rowptr2[v]);
    }
    const int e0 = rp[0];
    const int span = rp[4] - e0;
    const int cap = (span < 256) ? span : 256;

    // ---- phase A: cache csr span in SMEM (coalesced, chain-free) ----
    for (int k = lane; k < cap; k += 32) sidx[k] = __ldg(&g_csr[e0 + k]);
    __syncwarp();

    // ---- phase B: per-node row gathers, addresses from SMEM, 16 in flight ----
    #pragma unroll
    for (int n = 0; n < 4; n++) {
        int v = vbase + n;
        if (v >= NN) break;
        T z = GT<C>::load(h_in, v, lane);
        int b0 = rp[n] - e0, b1e = rp[n + 1] - e0;
        if (b1e <= cap) {
            int k = b0;
            for (; k + 16 <= b1e; k += 16) {
                T a[16];
                #pragma unroll
                for (int j = 0; j < 16; j++) a[j] = GT<C>::load(h_in, sidx[k + j], lane);
                T s01 = GT<C>::add(GT<C>::add(a[0], a[1]),  GT<C>::add(a[2], a[3]));
                T s23 = GT<C>::add(GT<C>::add(a[4], a[5]),  GT<C>::add(a[6], a[7]));
                T s45 = GT<C>::add(GT<C>::add(a[8], a[9]),  GT<C>::add(a[10], a[11]));
                T s67 = GT<C>::add(GT<C>::add(a[12], a[13]), GT<C>::add(a[14], a[15]));
                z = GT<C>::add(z, GT<C>::add(GT<C>::add(s01, s23), GT<C>::add(s45, s67)));
            }
            for (; k + 4 <= b1e; k += 4) {
                T a0 = GT<C>::load(h_in, sidx[k], lane);
                T a1 = GT<C>::load(h_in, sidx[k + 1], lane);
                T a2 = GT<C>::load(h_in, sidx[k + 2], lane);
                T a3 = GT<C>::load(h_in, sidx[k + 3], lane);
                z = GT<C>::add(z, GT<C>::add(GT<C>::add(a0, a1), GT<C>::add(a2, a3)));
            }
            for (; k < b1e; k++)
                z = GT<C>::add(z, GT<C>::load(h_in, sidx[k], lane));
        } else {
            for (int k = b0; k < b1e; k++)
                z = GT<C>::add(z, GT<C>::load(h_in, __ldg(&g_csr[e0 + k]), lane));
        }
        ((T*)zt)[n * 32 + lane] = z;
    }
    __syncwarp();

    // ---- GEMV1: t = relu(z @ W1 + b1) ----
    u64 acc[4];
    {
        u64 bias = ((const u64*)sb1)[lane];
        #pragma unroll
        for (int n = 0; n < 4; n++) acc[n] = bias;
    }
    for (int c4 = 0; c4 < C; c4 += 4) {
        float4 zq[4];
        #pragma unroll
        for (int n = 0; n < 4; n++)
            zq[n] = *(const float4*)&zt[n * C + c4];   // uniform broadcast
        #pragma unroll
        for (int k = 0; k < 4; k++) {
            u64 w = ((const u64*)(sW1 + (c4 + k) * 64))[lane];
            #pragma unroll
            for (int n = 0; n < 4; n++) {
                float zc = ((const float*)&zq[n])[k];
                acc[n] = fma2(splat2(zc), w, acc[n]);
            }
        }
    }
    __syncwarp();   // sidx reads done before tt overwrites (same region)
    #pragma unroll
    for (int n = 0; n < 4; n++) {
        float2 f = unpk(acc[n]);
        ((u64*)tt)[n * 32 + lane] = pk2(fmaxf(f.x, 0.f), fmaxf(f.y, 0.f));
    }
    __syncwarp();

    // ---- GEMV2: o = t @ W2 + b2 ----
    {
        u64 bias = ((const u64*)sb2)[lane];
        #pragma unroll
        for (int n = 0; n < 4; n++) acc[n] = bias;
    }
    for (int c4 = 0; c4 < 64; c4 += 4) {
        float4 zq[4];
        #pragma unroll
        for (int n = 0; n < 4; n++)
            zq[n] = *(const float4*)&tt[n * 64 + c4];
        #pragma unroll
        for (int k = 0; k < 4; k++) {
            u64 w = ((const u64*)(sW2 + (c4 + k) * 64))[lane];
            #pragma unroll
            for (int n = 0; n < 4; n++) {
                float zc = ((const float*)&zq[n])[k];
                acc[n] = fma2(splat2(zc), w, acc[n]);
            }
        }
    }

    if (POOL) {
        if (vbase + 3 < NN) {
            int ga = __ldg(&batch[vbase]);
            int gb = __ldg(&batch[vbase + 3]);
            if (ga == gb) {
                u64 s = add2(add2(acc[0], acc[1]), add2(acc[2], acc[3]));
                float2 f = unpk(s);
                atomicAdd((float2*)&g_pool[ga * 64 + 2 * lane], f);
                return;
            }
        }
        #pragma unroll
        for (int n = 0; n < 4; n++) {
            int v = vbase + n;
            if (v >= NN) break;
            int g = __ldg(&batch[v]);
            float2 f = unpk(acc[n]);
            atomicAdd((float2*)&g_pool[g * 64 + 2 * lane], f);
        }
    } else {
        #pragma unroll
        for (int n = 0; n < 4; n++) {
            int v = vbase + n;
            if (v >= NN) break;
            float2 f = unpk(acc[n]);
            if (RELU_OUT) { f.x = fmaxf(f.x, 0.f); f.y = fmaxf(f.y, 0.f); }
            ((u64*)(h_out + (size_t)v * 64))[lane] = pk2(f.x, f.y);
        }
    }
}

// ---------------- final linear ----------------
__global__ void final_kernel(const float* __restrict__ lin_w,
                             const float* __restrict__ lin_b,
                             float* __restrict__ out) {
    int gtid = blockIdx.x * blockDim.x + threadIdx.x;
    int g = gtid >> 5, lane = threadIdx.x & 31;
    if (g >= BB) return;
    float s = g_pool[g * 64 + lane] * __ldg(&lin_w[lane]) +
              g_pool[g * 64 + 32 + lane] * __ldg(&lin_w[32 + lane]);
    #pragma unroll
    for (int o = 16; o; o >>= 1) s += __shfl_xor_sync(0xffffffffu, s, o);
    if (lane == 0) {
        float cnt = (float)(g_end[g] - g_start[g]);
        out[g] = s / fmaxf(cnt, 1.f) + lin_b[0];
    }
}

// ---------------- launch ----------------
extern "C" void kernel_launch(void* const* d_in, const int* in_sizes, int n_in,
                              void* d_out, int out_size) {
    const float* x     = (const float*)d_in[0];
    const float* pos   = (const float*)d_in[1];
    const int*   ei    = (const int*)d_in[2];
    const int*   batch = (const int*)d_in[3];
    const float* W1f   = (const float*)d_in[4];
    const float* W1r   = (const float*)d_in[5];
    const float* b1    = (const float*)d_in[6];
    const float* W2    = (const float*)d_in[7];
    const float* b2    = (const float*)d_in[8];
    const float* lin_w = (const float*)d_in[9];
    const float* lin_b = (const float*)d_in[10];
    float* out = (float*)d_out;

    const int* src = ei;
    const int* dst = ei + EE;

    float *h0, *hA, *hB;
    cudaGetSymbolAddress((void**)&h0, g_h0);
    cudaGetSymbolAddress((void**)&hA, g_hA);
    cudaGetSymbolAddress((void**)&hB, g_hB);

    // smem (floats): W1 + W2 + 128 bias + 16 warps * 512
    const int smem32 = (32 * 64 + 4096 + 128 + 16 * 512) * 4;
    const int smem64 = (64 * 64 + 4096 + 128 + 16 * 512) * 4;
    cudaFuncSetAttribute((const void*)gin_layer<32, true,  false>, cudaFuncAttributeMaxDynamicSharedMemorySize, smem32);
    cudaFuncSetAttribute((const void*)gin_layer<64, true,  false>, cudaFuncAttributeMaxDynamicSharedMemorySize, smem64);
    cudaFuncSetAttribute((const void*)gin_layer<64, false, true>,  cudaFuncAttributeMaxDynamicSharedMemorySize, smem64);

    // 3 prologue launches -> launch #4 is the first gin_layer (profiled)
    fused_init<<<(NN * 32 + 255) / 256, 256>>>(x, pos, batch, dst, src);
    scanA_kernel<<<NSCAN_BLK, 1024>>>();
    scatter_fix<<<(EE + 255) / 256, 256>>>(src, dst);

    const int NB = (NN + 63) / 64;   // 64 nodes/block (16 warps x 4 nodes)

    gin_layer<32, true, false><<<NB, 512, smem32>>>(h0, hA, W1f, b1, W2, b2, batch);

    float* cur = hA;
    float* nxt = hB;
    for (int l = 1; l < LL; l++) {
        const float* w1 = W1r + (size_t)(l - 1) * HH * HH;
        if (l < LL - 1) {
            gin_layer<64, true, false><<<NB, 512, smem64>>>(cur, nxt, w1, b1 + l * HH,
                                                            W2 + (size_t)l * HH * HH, b2 + l * HH, batch);
            float* t = cur; cur = nxt; nxt = t;
        } else {
            gin_layer<64, false, true><<<NB, 512, smem64>>>(cur, nxt, w1, b1 + l * HH,
                                                            W2 + (size_t)l * HH * HH, b2 + l * HH, batch);
        }
    }

    final_kernel<<<(BB * 32 + 255) / 256, 256>>>(lin_w, lin_b, out);
}

// round 8
// speedup vs baseline: 1.9453x; 1.0483x over previous
#include <cuda_runtime.h>
#include <cuda_fp16.h>

#define NN 50000
#define EE 800000
#define HH 64
#define BB 50
#define LL 7
#define NSCAN_BLK 49   // ceil(50000/1024)

// ---------------- scratch (device globals; no allocations) ----------------
// NOTE: g_cursor must be zero at entry to each kernel_launch call. It is
// zero-initialized at load, and scatter_fix re-zeroes it every call, so the
// invariant holds across correctness run + every graph replay.
__device__ float   g_h0[NN * 32];      // layer-0 input (fp32)
__device__ __half2 g_hA[NN * 32];      // hidden ping (fp16x2, scaled)
__device__ __half2 g_hB[NN * 32];      // hidden pong (fp16x2, scaled)
__device__ int     g_rowptr[NN + 1];
__device__ int     g_rowptr2[NN + 1];
__device__ int     g_cursor[NN];
__device__ int     g_rank[EE];
__device__ int     g_csr[EE];
__device__ int     g_bsum[64];
__device__ float   g_pool[BB * 64];
__device__ int     g_start[BB];
__device__ int     g_end[BB];

// ---------------- f32x2 helpers ----------------
typedef unsigned long long u64;
__device__ __forceinline__ u64 splat2(float x) {
    u64 r; asm("mov.b64 %0,{%1,%1};" : "=l"(r) : "f"(x)); return r;
}
__device__ __forceinline__ u64 fma2(u64 a, u64 b, u64 c) {
    u64 d; asm("fma.rn.f32x2 %0,%1,%2,%3;" : "=l"(d) : "l"(a), "l"(b), "l"(c)); return d;
}
__device__ __forceinline__ u64 add2(u64 a, u64 b) {
    u64 d; asm("add.rn.f32x2 %0,%1,%2;" : "=l"(d) : "l"(a), "l"(b)); return d;
}
__device__ __forceinline__ float2 unpk(u64 v) {
    float2 f; asm("mov.b64 {%0,%1},%2;" : "=f"(f.x), "=f"(f.y) : "l"(v)); return f;
}
__device__ __forceinline__ u64 pk2(float x, float y) {
    u64 r; asm("mov.b64 %0,{%1,%2};" : "=l"(r) : "f"(x), "f"(y)); return r;
}
__device__ __forceinline__ float2 f2add(float2 a, float2 b) {
    a.x += b.x; a.y += b.y; return a;
}

// ---------------- launch 1: init + h0 + degree histogram ----------------
__global__ void fused_init(const float* __restrict__ x, const float* __restrict__ pos,
                           const int* __restrict__ batch, const int* __restrict__ dst) {
    int i = blockIdx.x * blockDim.x + threadIdx.x;
    if (i < NN * 32) {
        int v = i >> 5, c = i & 31;
        g_h0[i] = (c < 29) ? x[v * 29 + c] : pos[v * 3 + (c - 29)];
    }
    if (i < EE) {
        g_rank[i] = atomicAdd(&g_cursor[dst[i]], 1);
    }
    if (i < NN) {
        int bi = __ldg(&batch[i]);
        if (i == 0 || __ldg(&batch[i - 1]) != bi) g_start[bi] = i;
        if (i == NN - 1 || __ldg(&batch[i + 1]) != bi) g_end[bi] = i + 1;
    }
    if (i == 0) g_rowptr[0] = 0;
    if (i < BB * 64) g_pool[i] = 0.f;
}

// ---------------- launch 2: per-block scan of degrees ----------------
__global__ void scanA_kernel() {
    __shared__ int wsum[32];
    int i = blockIdx.x * 1024 + threadIdx.x;
    int lane = threadIdx.x & 31, wid = threadIdx.x >> 5;
    int xx = (i < NN) ? g_cursor[i] : 0;
    #pragma unroll
    for (int o = 1; o < 32; o <<= 1) {
        int y = __shfl_up_sync(0xffffffffu, xx, o);
        if (lane >= o) xx += y;
    }
    if (lane == 31) wsum[wid] = xx;
    __syncthreads();
    if (wid == 0) {
        int s = wsum[lane];
        #pragma unroll
        for (int o = 1; o < 32; o <<= 1) {
            int y = __shfl_up_sync(0xffffffffu, s, o);
            if (lane >= o) s += y;
        }
        wsum[lane] = s;
    }
    __syncthreads();
    int incl = xx + (wid ? wsum[wid - 1] : 0);
    if (i < NN) g_rowptr[i + 1] = incl;
    if (threadIdx.x == 1023) g_bsum[blockIdx.x] = incl;
}

// ---------------- launch 3: scatter + rowptr finalize + cursor re-zero ----------------
__global__ void scatter_fix(const int* __restrict__ src, const int* __restrict__ dst) {
    __shared__ int sb[NSCAN_BLK + 1];
    if (threadIdx.x < NSCAN_BLK) sb[threadIdx.x + 1] = g_bsum[threadIdx.x];
    __syncthreads();
    if (threadIdx.x == 0) {
        int run = 0;
        #pragma unroll
        for (int k = 0; k < NSCAN_BLK; k++) { int t = sb[k + 1]; sb[k] = run; run += t; }
    }
    __syncthreads();

    int e = blockIdx.x * blockDim.x + threadIdx.x;
    if (e <= NN) {
        int add = (e > 0) ? sb[(e - 1) >> 10] : 0;
        g_rowptr2[e] = g_rowptr[e] + add;
    }
    if (e < EE) {
        int d = dst[e];
        int base = g_rowptr[d] + ((d > 0) ? sb[(d - 1) >> 10] : 0);
        g_csr[base + g_rank[e]] = src[e];
    }
    if (e < NN) g_cursor[e] = 0;
}

// ---------------- fused GIN layer ----------------
// 16 warps/block, 4 nodes/warp. fp16x2 hidden state with per-layer rescaling:
//   stored h~_l = h_true / 4^(l+1); biases of layer l pre-multiplied by 4^-l;
//   outputs multiplied by store_scale=1/4 before fp16 store. ReLU commutes
//   with positive scaling; all arithmetic fp32, so only rounding is the store.
template <int C, bool RELU_OUT, bool POOL>
__global__ void __launch_bounds__(512) gin_layer(
    const void* __restrict__ h_in_v, __half2* __restrict__ h_out,
    const float* __restrict__ W1, const float* __restrict__ b1,
    const float* __restrict__ W2, const float* __restrict__ b2,
    const int* __restrict__ batch, float bias_scale, float store_scale)
{
    extern __shared__ float smem[];
    float* sW1 = smem;                    // C*64
    float* sW2 = sW1 + C * 64;            // 64*64
    float* sb1 = sW2 + 4096;              // 64
    float* sb2 = sb1 + 64;                // 64
    float* warpbase = sb2 + 64 + (threadIdx.x >> 5) * 512;
    float* zt = warpbase;                 // [0,256): z tile (4 x C)
    int*   sidx = (int*)(warpbase + 256); // [256,512): csr span cache (256 ints)
    float* tt = warpbase + 256;           // t tile reuses sidx region after gather

    for (int i = threadIdx.x; i < C * 64; i += 512) sW1[i] = W1[i];
    for (int i = threadIdx.x; i < 64 * 64; i += 512) sW2[i] = W2[i];
    if (threadIdx.x < 64) {
        sb1[threadIdx.x] = b1[threadIdx.x] * bias_scale;
        sb2[threadIdx.x] = b2[threadIdx.x] * bias_scale;
    }
    __syncthreads();

    const int lane  = threadIdx.x & 31;
    const int vbase = (blockIdx.x * 16 + (threadIdx.x >> 5)) * 4;

    // rowptrs for this warp's 4 nodes (clamped)
    int rp[5];
    #pragma unroll
    for (int k = 0; k < 5; k++) {
        int v = vbase + k; if (v > NN) v = NN;
        rp[k] = __ldg(&g_rowptr2[v]);
    }
    const int e0 = rp[0];
    const int span = rp[4] - e0;
    const int cap = (span < 256) ? span : 256;

    // ---- phase A: cache csr span in SMEM (coalesced, chain-free) ----
    for (int k = lane; k < cap; k += 32) sidx[k] = __ldg(&g_csr[e0 + k]);
    __syncwarp();

    // ---- phase B: per-node row gathers, 16 loads in flight ----
    if (C == 64) {
        const __half2* hp = (const __half2*)h_in_v;   // lane owns pair (2l,2l+1)
        #pragma unroll
        for (int n = 0; n < 4; n++) {
            int v = vbase + n;
            if (v >= NN) break;
            float2 z = __half22float2(__ldg(hp + (size_t)v * 32 + lane));
            int b0 = rp[n] - e0, b1e = rp[n + 1] - e0;
            if (b1e <= cap) {
                int k = b0;
                for (; k + 16 <= b1e; k += 16) {
                    float2 a[16];
                    #pragma unroll
                    for (int j = 0; j < 16; j++)
                        a[j] = __half22float2(__ldg(hp + (size_t)sidx[k + j] * 32 + lane));
                    float2 s0 = f2add(f2add(a[0], a[1]),   f2add(a[2], a[3]));
                    float2 s1 = f2add(f2add(a[4], a[5]),   f2add(a[6], a[7]));
                    float2 s2 = f2add(f2add(a[8], a[9]),   f2add(a[10], a[11]));
                    float2 s3 = f2add(f2add(a[12], a[13]), f2add(a[14], a[15]));
                    z = f2add(z, f2add(f2add(s0, s1), f2add(s2, s3)));
                }
                for (; k + 4 <= b1e; k += 4) {
                    float2 a0 = __half22float2(__ldg(hp + (size_t)sidx[k] * 32 + lane));
                    float2 a1 = __half22float2(__ldg(hp + (size_t)sidx[k + 1] * 32 + lane));
                    float2 a2 = __half22float2(__ldg(hp + (size_t)sidx[k + 2] * 32 + lane));
                    float2 a3 = __half22float2(__ldg(hp + (size_t)sidx[k + 3] * 32 + lane));
                    z = f2add(z, f2add(f2add(a0, a1), f2add(a2, a3)));
                }
                for (; k < b1e; k++)
                    z = f2add(z, __half22float2(__ldg(hp + (size_t)sidx[k] * 32 + lane)));
            } else {
                for (int k = b0; k < b1e; k++) {
                    int s = __ldg(&g_csr[e0 + k]);
                    z = f2add(z, __half22float2(__ldg(hp + (size_t)s * 32 + lane)));
                }
            }
            ((float2*)zt)[n * 32 + lane] = z;
        }
    } else {
        const float* hf = (const float*)h_in_v;       // lane owns feature l
        #pragma unroll
        for (int n = 0; n < 4; n++) {
            int v = vbase + n;
            if (v >= NN) break;
            float z = __ldg(hf + (size_t)v * 32 + lane);
            int b0 = rp[n] - e0, b1e = rp[n + 1] - e0;
            if (b1e <= cap) {
                int k = b0;
                for (; k + 16 <= b1e; k += 16) {
                    float a[16];
                    #pragma unroll
                    for (int j = 0; j < 16; j++)
                        a[j] = __ldg(hf + (size_t)sidx[k + j] * 32 + lane);
                    float s0 = (a[0] + a[1]) + (a[2] + a[3]);
                    float s1 = (a[4] + a[5]) + (a[6] + a[7]);
                    float s2 = (a[8] + a[9]) + (a[10] + a[11]);
                    float s3 = (a[12] + a[13]) + (a[14] + a[15]);
                    z += (s0 + s1) + (s2 + s3);
                }
                for (; k < b1e; k++)
                    z += __ldg(hf + (size_t)sidx[k] * 32 + lane);
            } else {
                for (int k = b0; k < b1e; k++)
                    z += __ldg(hf + (size_t)__ldg(&g_csr[e0 + k]) * 32 + lane);
            }
            zt[n * C + lane] = z;
        }
    }
    __syncwarp();

    // ---- GEMV1: t = relu(z @ W1 + b1*bias_scale) ----
    u64 acc[4];
    {
        u64 bias = ((const u64*)sb1)[lane];
        #pragma unroll
        for (int n = 0; n < 4; n++) acc[n] = bias;
    }
    for (int c4 = 0; c4 < C; c4 += 4) {
        float4 zq[4];
        #pragma unroll
        for (int n = 0; n < 4; n++)
            zq[n] = *(const float4*)&zt[n * C + c4];   // uniform broadcast
        #pragma unroll
        for (int k = 0; k < 4; k++) {
            u64 w = ((const u64*)(sW1 + (c4 + k) * 64))[lane];
            #pragma unroll
            for (int n = 0; n < 4; n++) {
                float zc = ((const float*)&zq[n])[k];
                acc[n] = fma2(splat2(zc), w, acc[n]);
            }
        }
    }
    __syncwarp();   // sidx reads done before tt overwrites (same region)
    #pragma unroll
    for (int n = 0; n < 4; n++) {
        float2 f = unpk(acc[n]);
        ((u64*)tt)[n * 32 + lane] = pk2(fmaxf(f.x, 0.f), fmaxf(f.y, 0.f));
    }
    __syncwarp();

    // ---- GEMV2: o = t @ W2 + b2*bias_scale ----
    {
        u64 bias = ((const u64*)sb2)[lane];
        #pragma unroll
        for (int n = 0; n < 4; n++) acc[n] = bias;
    }
    for (int c4 = 0; c4 < 64; c4 += 4) {
        float4 zq[4];
        #pragma unroll
        for (int n = 0; n < 4; n++)
            zq[n] = *(const float4*)&tt[n * 64 + c4];
        #pragma unroll
        for (int k = 0; k < 4; k++) {
            u64 w = ((const u64*)(sW2 + (c4 + k) * 64))[lane];
            #pragma unroll
            for (int n = 0; n < 4; n++) {
                float zc = ((const float*)&zq[n])[k];
                acc[n] = fma2(splat2(zc), w, acc[n]);
            }
        }
    }

    if (POOL) {
        if (vbase + 3 < NN) {
            int ga = __ldg(&batch[vbase]);
            int gb = __ldg(&batch[vbase + 3]);
            if (ga == gb) {
                u64 s = add2(add2(acc[0], acc[1]), add2(acc[2], acc[3]));
                float2 f = unpk(s);
                atomicAdd((float2*)&g_pool[ga * 64 + 2 * lane], f);
                return;
            }
        }
        #pragma unroll
        for (int n = 0; n < 4; n++) {
            int v = vbase + n;
            if (v >= NN) break;
            int g = __ldg(&batch[v]);
            float2 f = unpk(acc[n]);
            atomicAdd((float2*)&g_pool[g * 64 + 2 * lane], f);
        }
    } else {
        #pragma unroll
        for (int n = 0; n < 4; n++) {
            int v = vbase + n;
            if (v >= NN) break;
            float2 f = unpk(acc[n]);
            if (RELU_OUT) { f.x = fmaxf(f.x, 0.f); f.y = fmaxf(f.y, 0.f); }
            f.x *= store_scale; f.y *= store_scale;
            h_out[(size_t)v * 32 + lane] = __float22half2_rn(f);
        }
    }
}

// ---------------- final linear ----------------
// pooled sums are h_true * 4^-(LL-1); multiply back by 4^(LL-1) = 4096.
__global__ void final_kernel(const float* __restrict__ lin_w,
                             const float* __restrict__ lin_b,
                             float* __restrict__ out) {
    int gtid = blockIdx.x * blockDim.x + threadIdx.x;
    int g = gtid >> 5, lane = threadIdx.x & 31;
    if (g >= BB) return;
    float s = g_pool[g * 64 + lane] * __ldg(&lin_w[lane]) +
              g_pool[g * 64 + 32 + lane] * __ldg(&lin_w[32 + lane]);
    #pragma unroll
    for (int o = 16; o; o >>= 1) s += __shfl_xor_sync(0xffffffffu, s, o);
    if (lane == 0) {
        float cnt = (float)(g_end[g] - g_start[g]);
        out[g] = (s * 4096.0f) / fmaxf(cnt, 1.f) + lin_b[0];
    }
}

// ---------------- launch ----------------
extern "C" void kernel_launch(void* const* d_in, const int* in_sizes, int n_in,
                              void* d_out, int out_size) {
    const float* x     = (const float*)d_in[0];
    const float* pos   = (const float*)d_in[1];
    const int*   ei    = (const int*)d_in[2];
    const int*   batch = (const int*)d_in[3];
    const float* W1f   = (const float*)d_in[4];
    const float* W1r   = (const float*)d_in[5];
    const float* b1    = (const float*)d_in[6];
    const float* W2    = (const float*)d_in[7];
    const float* b2    = (const float*)d_in[8];
    const float* lin_w = (const float*)d_in[9];
    const float* lin_b = (const float*)d_in[10];
    float* out = (float*)d_out;

    const int* src = ei;
    const int* dst = ei + EE;

    void *h0, *hA, *hB;
    cudaGetSymbolAddress(&h0, g_h0);
    cudaGetSymbolAddress(&hA, g_hA);
    cudaGetSymbolAddress(&hB, g_hB);

    const int smem32 = (32 * 64 + 4096 + 128 + 16 * 512) * 4;
    const int smem64 = (64 * 64 + 4096 + 128 + 16 * 512) * 4;
    cudaFuncSetAttribute((const void*)gin_layer<32, true,  false>, cudaFuncAttributeMaxDynamicSharedMemorySize, smem32);
    cudaFuncSetAttribute((const void*)gin_layer<64, true,  false>, cudaFuncAttributeMaxDynamicSharedMemorySize, smem64);
    cudaFuncSetAttribute((const void*)gin_layer<64, false, true>,  cudaFuncAttributeMaxDynamicSharedMemorySize, smem64);

    // 3 prologue launches
    fused_init<<<(NN * 32 + 255) / 256, 256>>>(x, pos, batch, dst);
    scanA_kernel<<<NSCAN_BLK, 1024>>>();
    scatter_fix<<<(EE + 255) / 256, 256>>>(src, dst);

    const int NB = (NN + 63) / 64;   // 64 nodes/block (16 warps x 4 nodes)

    // layer 0: input fp32 unscaled -> bias_scale 1, store h~ = h/4
    gin_layer<32, true, false><<<NB, 512, smem32>>>(h0, (__half2*)hA, W1f, b1, W2, b2,
                                                    batch, 1.0f, 0.25f);

    void* cur = hA;
    void* nxt = hB;
    float bs = 0.25f;   // input scale of layer l is 4^-l
    for (int l = 1; l < LL; l++) {
        const float* w1 = W1r + (size_t)(l - 1) * HH * HH;
        if (l < LL - 1) {
            gin_layer<64, true, false><<<NB, 512, smem64>>>(cur, (__half2*)nxt, w1, b1 + l * HH,
                                                            W2 + (size_t)l * HH * HH, b2 + l * HH,
                                                            batch, bs, 0.25f);
            void* t = cur; cur = nxt; nxt = t;
        } else {
            gin_layer<64, false, true><<<NB, 512, smem64>>>(cur, (__half2*)nxt, w1, b1 + l * HH,
                                                            W2 + (size_t)l * HH * HH, b2 + l * HH,
                                                            batch, bs, 1.0f);
        }
        bs *= 0.25f;
    }

    final_kernel<<<(BB * 32 + 255) / 256, 256>>>(lin_w, lin_b, out);
}